// round 10
// baseline (speedup 1.0000x reference)
#include <cuda_runtime.h>
#include <cuda_bf16.h>
#include <cstdint>

// y[m, i2*32+i1] = sum_{j2,j1} x[m,j2*32+j1] * W2[i2,j2] * W1[i1,j1] + bias
// Per row m (one warp):
//   Stage1: T = X @ W1^T  (A = X frags straight from gmem via LDG.128 +
//                          k-permutation sigma; B = W1^T frags in regs)
//   Stage2: G = W2 @ T    (A = W2 frags in regs; B = T via movmatrix)
// tau makes each lane's outputs contiguous 32B -> coalesced STG.128.
// NEW (R10): depth-2 software pipeline — next row's X is loaded into
// registers while the current row computes, doubling per-warp MLP.
// mma.sync.m16n8k16 bf16, fp32 accuracy via 3-term hi/lo split.

typedef unsigned int u32;

#define RS 80                 // weight staging row stride (bytes)
#define NW 4                  // warps per CTA

__shared__ __align__(16) char swts[10240];     // W1h@0 W1l@2560 W2h@5120 W2l@7680
__shared__ __align__(16) float4 pbias4[256];   // [t][lane] tau/frag-permuted bias

__device__ __forceinline__ u32 smem_u32(const void* p) {
    u32 a;
    asm("{ .reg .u64 t; cvta.to.shared.u64 t, %1; cvt.u32.u64 %0, t; }"
        : "=r"(a) : "l"(p));
    return a;
}
__device__ __forceinline__ void ldm_x4(u32* r, u32 addr) {
    asm volatile("ldmatrix.sync.aligned.m8n8.x4.shared.b16 {%0,%1,%2,%3}, [%4];"
                 : "=r"(r[0]), "=r"(r[1]), "=r"(r[2]), "=r"(r[3]) : "r"(addr));
}
__device__ __forceinline__ u32 movm(u32 v) {
    u32 d;
    asm("movmatrix.sync.aligned.m8n8.trans.b16 %0, %1;" : "=r"(d) : "r"(v));
    return d;
}
__device__ __forceinline__ void mma_bf16(float* c, const u32* a, const u32* b) {
    asm volatile(
        "mma.sync.aligned.m16n8k16.row.col.f32.bf16.bf16.f32 "
        "{%0,%1,%2,%3}, {%4,%5,%6,%7}, {%8,%9}, {%0,%1,%2,%3};"
        : "+f"(c[0]), "+f"(c[1]), "+f"(c[2]), "+f"(c[3])
        : "r"(a[0]), "r"(a[1]), "r"(a[2]), "r"(a[3]), "r"(b[0]), "r"(b[1]));
}
// h = bf16x2(a -> low half, b -> high half); l = residuals
__device__ __forceinline__ void split2(float a, float b, u32& h, u32& l) {
    asm("cvt.rn.bf16x2.f32 %0, %1, %2;" : "=r"(h) : "f"(b), "f"(a));
    float ha = __uint_as_float(h << 16);
    float hb = __uint_as_float(h & 0xFFFF0000u);
    float ra = a - ha, rb = b - hb;
    asm("cvt.rn.bf16x2.f32 %0, %1, %2;" : "=r"(l) : "f"(rb), "f"(ra));
}
// split 32 floats, store hi/lo 64B rows at rowPtr / rowPtr+2560
__device__ __forceinline__ void split_store_row(char* rowPtr, const float* v) {
    u32 hw[16], lw[16];
#pragma unroll
    for (int p = 0; p < 16; p++) split2(v[2 * p], v[2 * p + 1], hw[p], lw[p]);
#pragma unroll
    for (int c = 0; c < 4; c++) {
        *(uint4*)(rowPtr + c * 16) =
            make_uint4(hw[4 * c], hw[4 * c + 1], hw[4 * c + 2], hw[4 * c + 3]);
        *(uint4*)(rowPtr + 2560 + c * 16) =
            make_uint4(lw[4 * c], lw[4 * c + 1], lw[4 * c + 2], lw[4 * c + 3]);
    }
}
// sigma: frag k-pos (within 16-block) -> physical col (within 16-block)
__device__ __forceinline__ int sigma16(int k) {
    return 4 * ((k & 7) >> 1) + 2 * (k >> 3) + (k & 1);
}
// tau: frag n-pos -> physical i1 col (involution, global 0..31)
__device__ __forceinline__ int tau32(int n) {
    return 8 * ((n & 7) >> 1) + 2 * (n >> 3) + (n & 1);
}
__device__ __forceinline__ void stg_cs(float* p, float4 v) {
    asm volatile("st.global.cs.v4.f32 [%0], {%1,%2,%3,%4};"
                 :: "l"(p), "f"(v.x), "f"(v.y), "f"(v.z), "f"(v.w) : "memory");
}

__global__ void __launch_bounds__(NW * 32, 3)
kron_mma6_kernel(const float* __restrict__ x,
                 const float* __restrict__ w1,
                 const float* __restrict__ w2,
                 const float* __restrict__ bias,
                 float* __restrict__ out,
                 int rows)
{
    const int tid  = threadIdx.x;
    const int lane = tid & 31;
    const int wrp  = tid >> 5;

    const int lq = lane >> 2;           // frag row within 8-block
    const int lr = lane & 3;            // quad index r

    const u32 laneOff = ((lane & 7) + 8 * ((lane >> 3) & 1)) * RS +
                        ((lane >> 4) << 4);

    // ---- one-time staging ----
    if (wrp == 0) {
        // M1[nu][c] = W1[tau(nu)][16*(c>>4)+sigma(c&15)]  (lane = nu)
        float v[32];
        const float* wrow = w1 + tau32(lane) * 32;
#pragma unroll
        for (int c = 0; c < 32; c++)
            v[c] = wrow[16 * (c >> 4) + sigma16(c & 15)];
        split_store_row(swts + 0 + lane * RS, v);
    } else if (wrp == 1) {
        // M2[i2][j2] = W2 row-major (identity perms on stage-2 M and K)
        float v[32];
        const float4* r = (const float4*)(w2 + lane * 32);
#pragma unroll
        for (int q = 0; q < 8; q++) {
            float4 t = r[q];
            v[4*q] = t.x; v[4*q+1] = t.y; v[4*q+2] = t.z; v[4*q+3] = t.w;
        }
        split_store_row(swts + 5120 + lane * RS, v);
    }
    // pbias4[t=mt*4+nt][lane]: physical (row 16mt+lq(+8), col 8*lr+2*nt, +1)
    for (int t = wrp; t < 8; t += NW) {
        int mt = t >> 2, nt = t & 3;
        int row = 16 * mt + lq;
        int col = 8 * lr + 2 * nt;
        pbias4[t * 32 + lane] =
            make_float4(bias[row * 32 + col], bias[row * 32 + col + 1],
                        bias[(row + 8) * 32 + col], bias[(row + 8) * 32 + col + 1]);
    }
    __syncthreads();

    // ---- invariant weight fragments in registers ----
    const u32 s0 = smem_u32(swts);
    u32 w1Bh[2][4][2], w1Bl[2][4][2];   // [kt][nt][reg]
#pragma unroll
    for (int a = 0; a < 2; a++)
#pragma unroll
        for (int b = 0; b < 2; b++) {
            u32 r[4];
            ldm_x4(r, s0 + 0 + a * (16 * RS) + b * 32 + laneOff);
            w1Bh[b][2*a][0] = r[0]; w1Bh[b][2*a+1][0] = r[1];
            w1Bh[b][2*a][1] = r[2]; w1Bh[b][2*a+1][1] = r[3];
            ldm_x4(r, s0 + 2560 + a * (16 * RS) + b * 32 + laneOff);
            w1Bl[b][2*a][0] = r[0]; w1Bl[b][2*a+1][0] = r[1];
            w1Bl[b][2*a][1] = r[2]; w1Bl[b][2*a+1][1] = r[3];
        }
    u32 w2Ah[2][2][4], w2Al[2][2][4];   // [mt][kt][4]
#pragma unroll
    for (int mt = 0; mt < 2; mt++)
#pragma unroll
        for (int kt = 0; kt < 2; kt++) {
            ldm_x4(w2Ah[mt][kt], s0 + 5120 + mt * (16 * RS) + kt * 32 + laneOff);
            ldm_x4(w2Al[mt][kt], s0 + 7680 + mt * (16 * RS) + kt * 32 + laneOff);
        }
    __syncthreads();

    const int gw = blockIdx.x * NW + wrp;
    const int nw = gridDim.x * NW;

    // base offsets for this lane's 8 LDG.128 per row
    const int xo0 = lq * 32 + 4 * lr;              // mt=0, kt=0
    // offsets: +0, +256(+8rows), +16(kt1), +272, +512(mt1), +768, +528, +784

    // ---- pipeline prologue: load row gw ----
    float4 xv[2][2][2];   // [mt][kt][h]
    if (gw < rows) {
        const float* xb = x + (size_t)gw * 1024;
#pragma unroll
        for (int mt = 0; mt < 2; mt++)
#pragma unroll
            for (int kt = 0; kt < 2; kt++) {
                int base = xo0 + mt * 512 + kt * 16;
                xv[mt][kt][0] = *(const float4*)(xb + base);
                xv[mt][kt][1] = *(const float4*)(xb + base + 256);
            }
    }

    for (int m = gw; m < rows; m += nw) {
        // ---- prefetch next row's X into separate registers ----
        float4 xn[2][2][2];
        const int mn = m + nw;
        if (mn < rows) {
            const float* xb = x + (size_t)mn * 1024;
#pragma unroll
            for (int mt = 0; mt < 2; mt++)
#pragma unroll
                for (int kt = 0; kt < 2; kt++) {
                    int base = xo0 + mt * 512 + kt * 16;
                    xn[mt][kt][0] = *(const float4*)(xb + base);
                    xn[mt][kt][1] = *(const float4*)(xb + base + 256);
                }
        }

        // ---- split current X into A-frags ----
        u32 XAh[2][2][4], XAl[2][2][4];
#pragma unroll
        for (int mt = 0; mt < 2; mt++)
#pragma unroll
            for (int kt = 0; kt < 2; kt++) {
                float4 u = xv[mt][kt][0], v = xv[mt][kt][1];
                split2(u.x, u.y, XAh[mt][kt][0], XAl[mt][kt][0]);
                split2(v.x, v.y, XAh[mt][kt][1], XAl[mt][kt][1]);
                split2(u.z, u.w, XAh[mt][kt][2], XAl[mt][kt][2]);
                split2(v.z, v.w, XAh[mt][kt][3], XAl[mt][kt][3]);
            }

        // ---- stage 1: T = X @ W1^T (3-term split) ----
        float acc[32];
#pragma unroll
        for (int i = 0; i < 32; i++) acc[i] = 0.f;
#pragma unroll
        for (int kt = 0; kt < 2; kt++)
#pragma unroll
            for (int mt = 0; mt < 2; mt++)
#pragma unroll
                for (int nt = 0; nt < 4; nt++) {
                    float* c = &acc[(mt * 4 + nt) * 4];
                    mma_bf16(c, XAh[mt][kt], w1Bh[kt][nt]);
                    mma_bf16(c, XAh[mt][kt], w1Bl[kt][nt]);
                    mma_bf16(c, XAl[mt][kt], w1Bh[kt][nt]);
                }

        // ---- T c-frags -> stage-2 B-frags via movmatrix ----
        u32 TBh[2][4][2], TBl[2][4][2];
#pragma unroll
        for (int kt = 0; kt < 2; kt++)
#pragma unroll
            for (int nt = 0; nt < 4; nt++) {
                float* c = &acc[(kt * 4 + nt) * 4];
                u32 h01, l01, h23, l23;
                split2(c[0], c[1], h01, l01);
                split2(c[2], c[3], h23, l23);
                TBh[kt][nt][0] = movm(h01);
                TBh[kt][nt][1] = movm(h23);
                TBl[kt][nt][0] = movm(l01);
                TBl[kt][nt][1] = movm(l23);
            }

        // ---- stage 2: G = W2 @ T, acc init = bias (8 LDS.128) ----
        float acc2[32];
#pragma unroll
        for (int t = 0; t < 8; t++) {
            float4 b4 = pbias4[t * 32 + lane];
            acc2[t*4+0] = b4.x; acc2[t*4+1] = b4.y;
            acc2[t*4+2] = b4.z; acc2[t*4+3] = b4.w;
        }
#pragma unroll
        for (int kt = 0; kt < 2; kt++)
#pragma unroll
            for (int mt = 0; mt < 2; mt++)
#pragma unroll
                for (int nt = 0; nt < 4; nt++) {
                    float* c = &acc2[(mt * 4 + nt) * 4];
                    mma_bf16(c, w2Ah[mt][kt], TBh[kt][nt]);
                    mma_bf16(c, w2Ah[mt][kt], TBl[kt][nt]);
                    mma_bf16(c, w2Al[mt][kt], TBh[kt][nt]);
                }

        // ---- store (streaming): tau gives 32B contiguous per lane ----
        float* ob = out + (size_t)m * 1024;
#pragma unroll
        for (int mt = 0; mt < 2; mt++)
#pragma unroll
            for (int h = 0; h < 2; h++) {
                int base = (16 * mt + 8 * h + lq) * 32 + 8 * lr;
                stg_cs(ob + base,
                    make_float4(acc2[(mt*4+0)*4 + 2*h], acc2[(mt*4+0)*4 + 2*h + 1],
                                acc2[(mt*4+1)*4 + 2*h], acc2[(mt*4+1)*4 + 2*h + 1]));
                stg_cs(ob + base + 4,
                    make_float4(acc2[(mt*4+2)*4 + 2*h], acc2[(mt*4+2)*4 + 2*h + 1],
                                acc2[(mt*4+3)*4 + 2*h], acc2[(mt*4+3)*4 + 2*h + 1]));
            }

        // ---- rotate pipeline ----
#pragma unroll
        for (int mt = 0; mt < 2; mt++)
#pragma unroll
            for (int kt = 0; kt < 2; kt++) {
                xv[mt][kt][0] = xn[mt][kt][0];
                xv[mt][kt][1] = xn[mt][kt][1];
            }
    }
}

extern "C" void kernel_launch(void* const* d_in, const int* in_sizes, int n_in,
                              void* d_out, int out_size) {
    const float* x    = (const float*)d_in[0];
    const float* w1   = (const float*)d_in[1];
    const float* w2   = (const float*)d_in[2];
    const float* bias = (const float*)d_in[3];
    float* out        = (float*)d_out;

    int rows = in_sizes[0] / 1024;    // 65536

    int grid = 592;                   // grid-stride persistent
    int maxg = (rows + NW - 1) / NW;
    if (grid > maxg) grid = maxg;
    kron_mma6_kernel<<<grid, NW * 32>>>(x, w1, w2, bias, out, rows);
}

// round 11
// speedup vs baseline: 1.1287x; 1.1287x over previous
#include <cuda_runtime.h>
#include <cuda_bf16.h>
#include <cstdint>

// y[m, i2*32+i1] = sum_{j2,j1} x[m,j2*32+j1] * W2[i2,j2] * W1[i1,j1] + bias
// Per row m (one warp):
//   Stage1: T = X @ W1^T  (A = X frags straight from gmem via LDG.128 +
//                          k-permutation sigma; B = W1^T frags in regs)
//   Stage2: G = W2 @ T    (A = W2 frags in regs; B = T via movmatrix)
// tau makes each lane's outputs contiguous 32B -> coalesced STG.128.
// R11: R9 config (128 regs, 16 warps/SM) + zero-register L2 prefetch of the
// next row (1 instruction/warp/iter) + streaming stores.
// mma.sync.m16n8k16 bf16, fp32 accuracy via 3-term hi/lo split.

typedef unsigned int u32;

#define RS 80                 // weight staging row stride (bytes)
#define NW 4                  // warps per CTA

__shared__ __align__(16) char swts[10240];     // W1h@0 W1l@2560 W2h@5120 W2l@7680
__shared__ __align__(16) float4 pbias4[256];   // [t][lane] tau/frag-permuted bias

__device__ __forceinline__ u32 smem_u32(const void* p) {
    u32 a;
    asm("{ .reg .u64 t; cvta.to.shared.u64 t, %1; cvt.u32.u64 %0, t; }"
        : "=r"(a) : "l"(p));
    return a;
}
__device__ __forceinline__ void ldm_x4(u32* r, u32 addr) {
    asm volatile("ldmatrix.sync.aligned.m8n8.x4.shared.b16 {%0,%1,%2,%3}, [%4];"
                 : "=r"(r[0]), "=r"(r[1]), "=r"(r[2]), "=r"(r[3]) : "r"(addr));
}
__device__ __forceinline__ u32 movm(u32 v) {
    u32 d;
    asm("movmatrix.sync.aligned.m8n8.trans.b16 %0, %1;" : "=r"(d) : "r"(v));
    return d;
}
__device__ __forceinline__ void mma_bf16(float* c, const u32* a, const u32* b) {
    asm volatile(
        "mma.sync.aligned.m16n8k16.row.col.f32.bf16.bf16.f32 "
        "{%0,%1,%2,%3}, {%4,%5,%6,%7}, {%8,%9}, {%0,%1,%2,%3};"
        : "+f"(c[0]), "+f"(c[1]), "+f"(c[2]), "+f"(c[3])
        : "r"(a[0]), "r"(a[1]), "r"(a[2]), "r"(a[3]), "r"(b[0]), "r"(b[1]));
}
// h = bf16x2(a -> low half, b -> high half); l = residuals
__device__ __forceinline__ void split2(float a, float b, u32& h, u32& l) {
    asm("cvt.rn.bf16x2.f32 %0, %1, %2;" : "=r"(h) : "f"(b), "f"(a));
    float ha = __uint_as_float(h << 16);
    float hb = __uint_as_float(h & 0xFFFF0000u);
    float ra = a - ha, rb = b - hb;
    asm("cvt.rn.bf16x2.f32 %0, %1, %2;" : "=r"(l) : "f"(rb), "f"(ra));
}
// split 32 floats, store hi/lo 64B rows at rowPtr / rowPtr+2560
__device__ __forceinline__ void split_store_row(char* rowPtr, const float* v) {
    u32 hw[16], lw[16];
#pragma unroll
    for (int p = 0; p < 16; p++) split2(v[2 * p], v[2 * p + 1], hw[p], lw[p]);
#pragma unroll
    for (int c = 0; c < 4; c++) {
        *(uint4*)(rowPtr + c * 16) =
            make_uint4(hw[4 * c], hw[4 * c + 1], hw[4 * c + 2], hw[4 * c + 3]);
        *(uint4*)(rowPtr + 2560 + c * 16) =
            make_uint4(lw[4 * c], lw[4 * c + 1], lw[4 * c + 2], lw[4 * c + 3]);
    }
}
// sigma: frag k-pos (within 16-block) -> physical col (within 16-block)
__device__ __forceinline__ int sigma16(int k) {
    return 4 * ((k & 7) >> 1) + 2 * (k >> 3) + (k & 1);
}
// tau: frag n-pos -> physical i1 col (involution, global 0..31)
__device__ __forceinline__ int tau32(int n) {
    return 8 * ((n & 7) >> 1) + 2 * (n >> 3) + (n & 1);
}
__device__ __forceinline__ void stg_cs(float* p, float4 v) {
    asm volatile("st.global.cs.v4.f32 [%0], {%1,%2,%3,%4};"
                 :: "l"(p), "f"(v.x), "f"(v.y), "f"(v.z), "f"(v.w) : "memory");
}
__device__ __forceinline__ void prefetch_l2(const void* p) {
    asm volatile("prefetch.global.L2 [%0];" :: "l"(p));
}

__global__ void __launch_bounds__(NW * 32)
kron_mma7_kernel(const float* __restrict__ x,
                 const float* __restrict__ w1,
                 const float* __restrict__ w2,
                 const float* __restrict__ bias,
                 float* __restrict__ out,
                 int rows)
{
    const int tid  = threadIdx.x;
    const int lane = tid & 31;
    const int wrp  = tid >> 5;

    const int lq = lane >> 2;           // frag row within 8-block
    const int lr = lane & 3;            // quad index r

    const u32 laneOff = ((lane & 7) + 8 * ((lane >> 3) & 1)) * RS +
                        ((lane >> 4) << 4);

    // ---- one-time staging ----
    if (wrp == 0) {
        // M1[nu][c] = W1[tau(nu)][16*(c>>4)+sigma(c&15)]  (lane = nu)
        float v[32];
        const float* wrow = w1 + tau32(lane) * 32;
#pragma unroll
        for (int c = 0; c < 32; c++)
            v[c] = wrow[16 * (c >> 4) + sigma16(c & 15)];
        split_store_row(swts + 0 + lane * RS, v);
    } else if (wrp == 1) {
        // M2[i2][j2] = W2 row-major (identity perms on stage-2 M and K)
        float v[32];
        const float4* r = (const float4*)(w2 + lane * 32);
#pragma unroll
        for (int q = 0; q < 8; q++) {
            float4 t = r[q];
            v[4*q] = t.x; v[4*q+1] = t.y; v[4*q+2] = t.z; v[4*q+3] = t.w;
        }
        split_store_row(swts + 5120 + lane * RS, v);
    }
    // pbias4[t=mt*4+nt][lane]: physical (row 16mt+lq(+8), col 8*lr+2*nt, +1)
    for (int t = wrp; t < 8; t += NW) {
        int mt = t >> 2, nt = t & 3;
        int row = 16 * mt + lq;
        int col = 8 * lr + 2 * nt;
        pbias4[t * 32 + lane] =
            make_float4(bias[row * 32 + col], bias[row * 32 + col + 1],
                        bias[(row + 8) * 32 + col], bias[(row + 8) * 32 + col + 1]);
    }
    __syncthreads();

    // ---- invariant weight fragments in registers ----
    const u32 s0 = smem_u32(swts);
    u32 w1Bh[2][4][2], w1Bl[2][4][2];   // [kt][nt][reg]
#pragma unroll
    for (int a = 0; a < 2; a++)
#pragma unroll
        for (int b = 0; b < 2; b++) {
            u32 r[4];
            ldm_x4(r, s0 + 0 + a * (16 * RS) + b * 32 + laneOff);
            w1Bh[b][2*a][0] = r[0]; w1Bh[b][2*a+1][0] = r[1];
            w1Bh[b][2*a][1] = r[2]; w1Bh[b][2*a+1][1] = r[3];
            ldm_x4(r, s0 + 2560 + a * (16 * RS) + b * 32 + laneOff);
            w1Bl[b][2*a][0] = r[0]; w1Bl[b][2*a+1][0] = r[1];
            w1Bl[b][2*a][1] = r[2]; w1Bl[b][2*a+1][1] = r[3];
        }
    u32 w2Ah[2][2][4], w2Al[2][2][4];   // [mt][kt][4]
#pragma unroll
    for (int mt = 0; mt < 2; mt++)
#pragma unroll
        for (int kt = 0; kt < 2; kt++) {
            ldm_x4(w2Ah[mt][kt], s0 + 5120 + mt * (16 * RS) + kt * 32 + laneOff);
            ldm_x4(w2Al[mt][kt], s0 + 7680 + mt * (16 * RS) + kt * 32 + laneOff);
        }
    __syncthreads();

    const int gw = blockIdx.x * NW + wrp;
    const int nw = gridDim.x * NW;

    // prefetch the first row (whole 4KB: lane covers line `lane`)
    if (gw < rows)
        prefetch_l2(x + (size_t)gw * 1024 + lane * 32);

    for (int m = gw; m < rows; m += nw) {
        const float* xb = x + (size_t)m * 1024;

        // ---- zero-reg L2 prefetch of the NEXT row (1 instr covers 4KB) ----
        const int mn = m + nw;
        if (mn < rows)
            prefetch_l2(x + (size_t)mn * 1024 + lane * 32);

        // ---- X A-frags: 8 LDG.128 (L2 hits thanks to prefetch) ----
        float4 xv[2][2][2];   // [mt][kt][h]
#pragma unroll
        for (int mt = 0; mt < 2; mt++)
#pragma unroll
            for (int kt = 0; kt < 2; kt++) {
                int base = (16 * mt + lq) * 32 + 16 * kt + 4 * lr;
                xv[mt][kt][0] = *(const float4*)(xb + base);
                xv[mt][kt][1] = *(const float4*)(xb + base + 256);  // +8 rows
            }
        u32 XAh[2][2][4], XAl[2][2][4];
#pragma unroll
        for (int mt = 0; mt < 2; mt++)
#pragma unroll
            for (int kt = 0; kt < 2; kt++) {
                float4 u = xv[mt][kt][0], v = xv[mt][kt][1];
                split2(u.x, u.y, XAh[mt][kt][0], XAl[mt][kt][0]);
                split2(v.x, v.y, XAh[mt][kt][1], XAl[mt][kt][1]);
                split2(u.z, u.w, XAh[mt][kt][2], XAl[mt][kt][2]);
                split2(v.z, v.w, XAh[mt][kt][3], XAl[mt][kt][3]);
            }

        // ---- stage 1: T = X @ W1^T (3-term split) ----
        float acc[32];
#pragma unroll
        for (int i = 0; i < 32; i++) acc[i] = 0.f;
#pragma unroll
        for (int kt = 0; kt < 2; kt++)
#pragma unroll
            for (int mt = 0; mt < 2; mt++)
#pragma unroll
                for (int nt = 0; nt < 4; nt++) {
                    float* c = &acc[(mt * 4 + nt) * 4];
                    mma_bf16(c, XAh[mt][kt], w1Bh[kt][nt]);
                    mma_bf16(c, XAh[mt][kt], w1Bl[kt][nt]);
                    mma_bf16(c, XAl[mt][kt], w1Bh[kt][nt]);
                }

        // ---- T c-frags -> stage-2 B-frags via movmatrix ----
        u32 TBh[2][4][2], TBl[2][4][2];
#pragma unroll
        for (int kt = 0; kt < 2; kt++)
#pragma unroll
            for (int nt = 0; nt < 4; nt++) {
                float* c = &acc[(kt * 4 + nt) * 4];
                u32 h01, l01, h23, l23;
                split2(c[0], c[1], h01, l01);
                split2(c[2], c[3], h23, l23);
                TBh[kt][nt][0] = movm(h01);
                TBh[kt][nt][1] = movm(h23);
                TBl[kt][nt][0] = movm(l01);
                TBl[kt][nt][1] = movm(l23);
            }

        // ---- stage 2: G = W2 @ T, acc init = bias (8 LDS.128) ----
        float acc2[32];
#pragma unroll
        for (int t = 0; t < 8; t++) {
            float4 b4 = pbias4[t * 32 + lane];
            acc2[t*4+0] = b4.x; acc2[t*4+1] = b4.y;
            acc2[t*4+2] = b4.z; acc2[t*4+3] = b4.w;
        }
#pragma unroll
        for (int kt = 0; kt < 2; kt++)
#pragma unroll
            for (int mt = 0; mt < 2; mt++)
#pragma unroll
                for (int nt = 0; nt < 4; nt++) {
                    float* c = &acc2[(mt * 4 + nt) * 4];
                    mma_bf16(c, w2Ah[mt][kt], TBh[kt][nt]);
                    mma_bf16(c, w2Ah[mt][kt], TBl[kt][nt]);
                    mma_bf16(c, w2Al[mt][kt], TBh[kt][nt]);
                }

        // ---- store (streaming): tau gives 32B contiguous per lane ----
        float* ob = out + (size_t)m * 1024;
#pragma unroll
        for (int mt = 0; mt < 2; mt++)
#pragma unroll
            for (int h = 0; h < 2; h++) {
                int base = (16 * mt + 8 * h + lq) * 32 + 8 * lr;
                stg_cs(ob + base,
                    make_float4(acc2[(mt*4+0)*4 + 2*h], acc2[(mt*4+0)*4 + 2*h + 1],
                                acc2[(mt*4+1)*4 + 2*h], acc2[(mt*4+1)*4 + 2*h + 1]));
                stg_cs(ob + base + 4,
                    make_float4(acc2[(mt*4+2)*4 + 2*h], acc2[(mt*4+2)*4 + 2*h + 1],
                                acc2[(mt*4+3)*4 + 2*h], acc2[(mt*4+3)*4 + 2*h + 1]));
            }
    }
}

extern "C" void kernel_launch(void* const* d_in, const int* in_sizes, int n_in,
                              void* d_out, int out_size) {
    const float* x    = (const float*)d_in[0];
    const float* w1   = (const float*)d_in[1];
    const float* w2   = (const float*)d_in[2];
    const float* bias = (const float*)d_in[3];
    float* out        = (float*)d_out;

    int rows = in_sizes[0] / 1024;    // 65536

    int grid = 592;                   // 4 CTAs/SM, grid-stride persistent
    int maxg = (rows + NW - 1) / NW;
    if (grid > maxg) grid = maxg;
    kron_mma7_kernel<<<grid, NW * 32>>>(x, w1, w2, bias, out, rows);
}